// round 7
// baseline (speedup 1.0000x reference)
#include <cuda_runtime.h>
#include <cstdint>

#define Bv    32
#define Nv    8192
#define DIN   64
#define DOUT  128
#define NRING 4
#define TILE  256

// Scratch (no allocs allowed): folded weights, per-(b,ring,o) ordered-int max, finals.
__device__ __align__(16) float g_Wt[NRING][DIN][DOUT]; // W[r][o][k]*scale, transposed to [r][k][o]
__device__ float g_beff[NRING][DOUT];        // (b-mean)*scale + beta
__device__ int   g_rmax[Bv][NRING][DOUT];    // ordered-int encoded running max of dot
__device__ float g_final[Bv][NRING][DOUT];   // decoded max + beff
__device__ int   g_ring64;                   // 1 if ring buffer is int64, 0 if int32

__device__ __forceinline__ int fkey(float f) {
    int i = __float_as_int(f);
    return i >= 0 ? i : (i ^ 0x7fffffff);
}
__device__ __forceinline__ float dekey(int k) {
    return __int_as_float(k >= 0 ? k : (k ^ 0x7fffffff));
}
__device__ __forceinline__ int get_ring(const void* ring, size_t idx, int is64) {
    if (is64) return (int)((const long long*)ring)[idx];
    return ((const int*)ring)[idx];
}

// ---------------------------------------------------------------------------
// Detect ring dtype. If the buffer is int32, an int64-interpreted read is
// lo + (hi<<32) with lo,hi in [0,4): out of [0,NRING) unless hi==0 for every
// scanned pair — vanishingly improbable over 2048 entries. Reads 16KB, which
// is in bounds under either dtype (buffer is >= 1MB).
// ---------------------------------------------------------------------------
__global__ void k_detect(const void* __restrict__ ring) {
    const long long* r64 = (const long long*)ring;
    int bad = 0;
    for (int i = threadIdx.x; i < 2048; i += 32) {
        long long v = r64[i];
        if (v < 0 || v >= NRING) bad = 1;
    }
    bad = __any_sync(0xffffffffu, bad);
    if (threadIdx.x == 0) g_ring64 = bad ? 0 : 1;
}

// ---------------------------------------------------------------------------
// Fold BN scale into W, compute effective bias, init max buffer.
// 512 threads: one per (r,o).
// ---------------------------------------------------------------------------
__global__ void k_fold(const float* __restrict__ W, const float* __restrict__ bvec,
                       const float* __restrict__ gamma, const float* __restrict__ beta,
                       const float* __restrict__ mean, const float* __restrict__ var) {
    int t = threadIdx.x;          // 0..511
    int r = t >> 7;
    int o = t & 127;
    float s = gamma[t] * rsqrtf(var[t] + 1e-5f);
    g_beff[r][o] = (bvec[t] - mean[t]) * s + beta[t];
#pragma unroll 8
    for (int k = 0; k < DIN; k++)
        g_Wt[r][k][o] = W[t * DIN + k] * s;
#pragma unroll
    for (int b = 0; b < Bv; b++)
        g_rmax[b][r][o] = 0x80000000;   // INT_MIN
}

// ---------------------------------------------------------------------------
// K1: per-(b,ring,o) max of dot(Weff[r,o,:], x[b,:,n]).
// CTA = 256-point tile of one batch. Points bucketed by ring in smem; 2 warps
// per ring; each thread: 4 output channels (lane*4..+3) x 8 same-ring points.
// W via LDG.128 (L1-resident, 1 load / 32 FMA), x via smem broadcast.
// ---------------------------------------------------------------------------
extern __shared__ unsigned char smraw[];

__global__ void __launch_bounds__(TILE) k_reduce(const float* __restrict__ x,
                                                 const void* __restrict__ ring) {
    float* xs = (float*)smraw;                                        // [DIN][TILE] 64KB
    unsigned short* lst = (unsigned short*)(smraw + DIN * TILE * 4);  // [NRING][TILE]
    int* cnt = (int*)(smraw + DIN * TILE * 4 + NRING * TILE * 2);     // [NRING]

    int b  = blockIdx.y;
    int n0 = blockIdx.x * TILE;
    int tid = threadIdx.x;
    int is64 = g_ring64;

    if (tid < NRING) cnt[tid] = 0;
    __syncthreads();

    // bucket points by ring
    {
        int r = get_ring(ring, (size_t)b * Nv + n0 + tid, is64);
        int pos = atomicAdd(&cnt[r], 1);
        lst[r * TILE + pos] = (unsigned short)tid;
    }
    // stage x tile (coalesced)
    {
        const float* xb = x + (size_t)b * DIN * Nv + n0;
        for (int i = tid; i < DIN * TILE; i += TILE) {
            int k = i >> 8;
            int j = i & 255;
            xs[k * TILE + j] = xb[(size_t)k * Nv + j];
        }
    }
    __syncthreads();

    int w = tid >> 5, lane = tid & 31;
    int r = w >> 1, h = w & 1;          // 2 warps per ring
    int L = cnt[r];

    const float4* Wp = (const float4*)(&g_Wt[r][0][0]);  // [DIN][32] float4 rows

    float m0 = -3.402823466e38f, m1 = m0, m2 = m0, m3 = m0;

    for (int base = h * 8; base < L; base += 16) {
        int pidx[8];
#pragma unroll
        for (int i = 0; i < 8; i++) {
            int ii = base + i;
            pidx[i] = lst[r * TILE + (ii < L ? ii : base)];  // pad with dup (max-safe)
        }
        float acc[8][4];
#pragma unroll
        for (int p = 0; p < 8; p++) {
            acc[p][0] = 0.f; acc[p][1] = 0.f; acc[p][2] = 0.f; acc[p][3] = 0.f;
        }
#pragma unroll 8
        for (int k = 0; k < DIN; k++) {
            float4 wv = Wp[k * 32 + lane];
#pragma unroll
            for (int p = 0; p < 8; p++) {
                float xv = xs[k * TILE + pidx[p]];
                acc[p][0] = fmaf(wv.x, xv, acc[p][0]);
                acc[p][1] = fmaf(wv.y, xv, acc[p][1]);
                acc[p][2] = fmaf(wv.z, xv, acc[p][2]);
                acc[p][3] = fmaf(wv.w, xv, acc[p][3]);
            }
        }
#pragma unroll
        for (int p = 0; p < 8; p++) {
            m0 = fmaxf(m0, acc[p][0]);
            m1 = fmaxf(m1, acc[p][1]);
            m2 = fmaxf(m2, acc[p][2]);
            m3 = fmaxf(m3, acc[p][3]);
        }
    }

    if (L > 0) {
        int* dst = &g_rmax[b][r][lane * 4];
        atomicMax(&dst[0], fkey(m0));
        atomicMax(&dst[1], fkey(m1));
        atomicMax(&dst[2], fkey(m2));
        atomicMax(&dst[3], fkey(m3));
    }
}

// ---------------------------------------------------------------------------
// Decode max keys + add effective bias.
// ---------------------------------------------------------------------------
__global__ void k_finalize() {
    int i = blockIdx.x * blockDim.x + threadIdx.x;  // < Bv*NRING*DOUT = 16384
    int key = ((const int*)g_rmax)[i];
    float v = 0.0f;
    if (key != (int)0x80000000)
        v = dekey(key) + ((const float*)g_beff)[i & (NRING * DOUT - 1)];
    ((float*)g_final)[i] = v;
}

// ---------------------------------------------------------------------------
// K2: out[b,o,n] = g_final[b, ring[b,n], o]. Coalesced over n per o-iteration.
// ---------------------------------------------------------------------------
__global__ void __launch_bounds__(256) k_broadcast(const void* __restrict__ ring,
                                                   float* __restrict__ out) {
    __shared__ float fs[NRING][DOUT + 4];   // pad to avoid bank conflicts
    int b = blockIdx.y;
    int tid = threadIdx.x;
    int is64 = g_ring64;
    for (int i = tid; i < NRING * DOUT; i += 256) {
        int r = i >> 7, o = i & 127;
        fs[r][o] = g_final[b][r][o];
    }
    __syncthreads();

    int n = blockIdx.x * 256 + tid;
    int r = get_ring(ring, (size_t)b * Nv + n, is64);
    const float* f = &fs[r][0];
    float* ob = out + (size_t)b * DOUT * Nv + n;
#pragma unroll
    for (int o = 0; o < DOUT; o++)
        ob[(size_t)o * Nv] = f[o];
}

// ---------------------------------------------------------------------------
extern "C" void kernel_launch(void* const* d_in, const int* in_sizes, int n_in,
                              void* d_out, int out_size) {
    // Identify x / ring / W by their unique element counts; the five 512-elem
    // vectors keep their given relative order: b, gamma, beta, mean, var.
    const float* x    = nullptr;
    const void*  ring = nullptr;
    const float* W    = nullptr;
    const float* vec5[5] = {nullptr, nullptr, nullptr, nullptr, nullptr};
    int nv5 = 0;
    for (int i = 0; i < n_in; i++) {
        int s = in_sizes[i];
        if      (s == Bv * DIN * Nv)      x    = (const float*)d_in[i];
        else if (s == Bv * Nv)            ring = d_in[i];
        else if (s == NRING * DOUT * DIN) W    = (const float*)d_in[i];
        else if (s == NRING * DOUT && nv5 < 5) vec5[nv5++] = (const float*)d_in[i];
    }
    const float* bvec  = vec5[0];
    const float* gamma = vec5[1];
    const float* beta  = vec5[2];
    const float* mean  = vec5[3];
    const float* var   = vec5[4];
    float* out = (float*)d_out;
    (void)out_size;

    static int smem_sz = DIN * TILE * 4 + NRING * TILE * 2 + NRING * 4;
    cudaFuncSetAttribute(k_reduce, cudaFuncAttributeMaxDynamicSharedMemorySize, smem_sz);

    k_detect<<<1, 32>>>(ring);

    k_fold<<<1, NRING * DOUT>>>(W, bvec, gamma, beta, mean, var);

    dim3 g1(Nv / TILE, Bv);
    k_reduce<<<g1, TILE, smem_sz>>>(x, ring);

    k_finalize<<<(Bv * NRING * DOUT) / 256, 256>>>();

    dim3 g2(Nv / 256, Bv);
    k_broadcast<<<g2, 256>>>(ring, out);
}